// round 10
// baseline (speedup 1.0000x reference)
#include <cuda_runtime.h>
#include <cstdint>

// Problem constants (fixed by the reference: B=2, V=2000, F=800, 128x128, K=4)
#define IMG     128
#define NPIX    (IMG * IMG)
#define NFACE   800
#define NB      2
#define NV      2000
#define KTOP    4
#define EPSF    1e-8f
#define BLURF   0.01f
#define MARGIN  0.101f               // sqrt(BLURF)=0.1 plus fp slack (conservative)
#define FSTRIDE 20                   // floats per face record (5 x float4)

#define PPB     224                  // pixels per block (7 spans of 32)
#define NSLICE  4                    // face quarters / threads per pixel
#define TPB     (PPB * NSLICE)       // 896 threads = 28 warps
#define NSPAN   7
#define BLKX    74                   // 74 * 224 = 16576 >= 16384
#define FQUART  (NFACE / NSLICE)     // 200 faces per quarter

// Shared memory layout (bytes):
//   [0,      64000)   face records   (800 * 20 floats)
//   [64000,  76800)   expanded bbox  (800 * float4)
//   [76800, 115200)   edge cull eqs  (800 * 3 float4)
//   [115200,126400)   span survivor lists (7 spans * 800 uint16, 4 segments each)
//   [126400,126512)   counts (7 spans * 4 quarters ints)
//   [126512,155184)   merge buffer   (224 pixels * 16 * uint64)
#define BB_OFF      (NFACE * FSTRIDE)
#define EDGE_BYTE   (NFACE * FSTRIDE * 4 + NFACE * 16)   // 76800
#define LIST_BYTE   (EDGE_BYTE + NFACE * 48)             // 115200
#define CNT_BYTE    (LIST_BYTE + NSPAN * NFACE * 2)      // 126400
#define MRG_BYTE    (CNT_BYTE + NSPAN * NSLICE * 4)      // 126512
#define SMEM_BYTES  (MRG_BYTE + PPB * 16 * 8)            // 155184

// Output layout (float32, concatenated flattened reference outputs)
#define OFF_ZBUF  131072
#define OFF_BARY  262144
#define OFF_DIST  655360

struct FaceEval {
    float b0, b1, b2, zpix, dsign;
    bool  valid;
};

__device__ __forceinline__ float seg_dist2(float pax, float pay,
                                           float abx, float aby, float rl) {
    float num = __fadd_rn(__fmul_rn(pax, abx), __fmul_rn(pay, aby));
    float t   = __fmul_rn(num, rl);
    t = fminf(fmaxf(t, 0.0f), 1.0f);
    float dx = __fsub_rn(pax, __fmul_rn(t, abx));
    float dy = __fsub_rn(pay, __fmul_rn(t, aby));
    return __fadd_rn(__fmul_rn(dx, dx), __fmul_rn(dy, dy));
}

// Field map (5 x float4 per face):
//  q0: a0x a0y a1x a1y
//  q1: a2x a2y dx01 dy01
//  q2: dx12 dy12 dx20 dy20
//  q3: z0 z1 z2 rdenom
//  q4: rl01 rl12 rl20 areaflag
__device__ __forceinline__ FaceEval eval_face(const float4* __restrict__ fq5,
                                              float px, float py) {
    float4 q0 = fq5[0];
    float4 q1 = fq5[1];
    float4 q2 = fq5[2];
    float4 q3 = fq5[3];
    float4 q4 = fq5[4];

    float pa0x = __fsub_rn(px, q0.x), pa0y = __fsub_rn(py, q0.y);
    float pa1x = __fsub_rn(px, q0.z), pa1y = __fsub_rn(py, q0.w);
    float pa2x = __fsub_rn(px, q1.x), pa2y = __fsub_rn(py, q1.y);

    float w0 = __fsub_rn(__fmul_rn(pa1x, q2.y), __fmul_rn(pa1y, q2.x));
    float w1 = __fsub_rn(__fmul_rn(pa2x, q2.w), __fmul_rn(pa2y, q2.z));
    float w2 = __fsub_rn(__fmul_rn(pa0x, q1.w), __fmul_rn(pa0y, q1.z));

    FaceEval e;
    float rd = q3.w;
    e.b0 = __fmul_rn(w0, rd);
    e.b1 = __fmul_rn(w1, rd);
    e.b2 = __fmul_rn(w2, rd);

    e.zpix = __fadd_rn(__fadd_rn(__fmul_rn(e.b0, q3.x), __fmul_rn(e.b1, q3.y)),
                       __fmul_rn(e.b2, q3.z));

    bool inside = (e.b0 >= 0.0f) && (e.b1 >= 0.0f) && (e.b2 >= 0.0f);

    float d01 = seg_dist2(pa0x, pa0y, q1.z, q1.w, q4.x);
    float d12 = seg_dist2(pa1x, pa1y, q2.x, q2.y, q4.y);
    float d20 = seg_dist2(pa2x, pa2y, q2.z, q2.w, q4.z);
    float dmin = fminf(d01, fminf(d12, d20));

    e.dsign = inside ? -dmin : dmin;
    e.valid = (inside || (dmin < BLURF)) && (e.zpix > EPSF) && (q4.w > 0.5f);
    return e;
}

__global__ void __launch_bounds__(TPB, 1)
raster_kernel(const float* __restrict__ verts,
              const int*   __restrict__ faces,
              float*       __restrict__ out) {
    extern __shared__ float sf[];
    const int b    = blockIdx.y;
    const int tid  = threadIdx.x;
    const int lane = tid & 31;

    const int pixLocal = tid % PPB;        // 0..223
    const int slice    = tid / PPB;        // 0..3  (face quarter)
    const int span     = pixLocal >> 5;    // 0..6  (32-pixel span)
    // NOTE: warp id == slice*7 + span, so each warp has uniform (span, slice).

    // ---- Phase 1: per-face records + bbox + dilated-edge separation eqs
    const float* vb = verts + (size_t)b * NV * 3;
    for (int f = tid; f < NFACE; f += TPB) {
        int i0 = faces[3 * f + 0];
        int i1 = faces[3 * f + 1];
        int i2 = faces[3 * f + 2];
        float a0x = vb[3 * i0], a0y = vb[3 * i0 + 1], z0 = vb[3 * i0 + 2];
        float a1x = vb[3 * i1], a1y = vb[3 * i1 + 1], z1 = vb[3 * i1 + 2];
        float a2x = vb[3 * i2], a2y = vb[3 * i2 + 1], z2 = vb[3 * i2 + 2];

        float dx01 = __fsub_rn(a1x, a0x), dy01 = __fsub_rn(a1y, a0y);
        float dx12 = __fsub_rn(a2x, a1x), dy12 = __fsub_rn(a2y, a1y);
        float dx20 = __fsub_rn(a0x, a2x), dy20 = __fsub_rn(a0y, a2y);

        float area = __fsub_rn(__fmul_rn(__fsub_rn(a2x, a0x), dy01),
                               __fmul_rn(__fsub_rn(a2y, a0y), dx01));
        bool  big   = fabsf(area) > EPSF;
        float denom = big ? area : ((area >= 0.0f) ? EPSF : -EPSF);

        float l01 = __fadd_rn(__fadd_rn(__fmul_rn(dx01, dx01), __fmul_rn(dy01, dy01)), EPSF);
        float l12 = __fadd_rn(__fadd_rn(__fmul_rn(dx12, dx12), __fmul_rn(dy12, dy12)), EPSF);
        float l20 = __fadd_rn(__fadd_rn(__fmul_rn(dx20, dx20), __fmul_rn(dy20, dy20)), EPSF);

        float* d = sf + f * FSTRIDE;
        d[0]  = a0x;  d[1]  = a0y;  d[2]  = a1x;  d[3]  = a1y;
        d[4]  = a2x;  d[5]  = a2y;  d[6]  = dx01; d[7]  = dy01;
        d[8]  = dx12; d[9]  = dy12; d[10] = dx20; d[11] = dy20;
        d[12] = z0;   d[13] = z1;   d[14] = z2;   d[15] = 1.0f / denom;
        d[16] = 1.0f / l01; d[17] = 1.0f / l12; d[18] = 1.0f / l20;
        d[19] = big ? 1.0f : 0.0f;

        // bbox (expanded). Degenerate faces are never valid -> empty bbox culls
        // them here, so the scan never sees them (no flag check needed there).
        float xmn, xmx, ymn, ymx;
        if (big) {
            xmn = fminf(a0x, fminf(a1x, a2x)) - MARGIN;
            xmx = fmaxf(a0x, fmaxf(a1x, a2x)) + MARGIN;
            ymn = fminf(a0y, fminf(a1y, a2y)) - MARGIN;
            ymx = fmaxf(a0y, fmaxf(a1y, a2y)) + MARGIN;
        } else {
            xmn = 1e30f; xmx = -1e30f; ymn = 1e30f; ymx = -1e30f;
        }
        float* bb = sf + BB_OFF + f * 4;
        bb[0] = xmn; bb[1] = xmx; bb[2] = ymn; bb[3] = ymx;

        // Dilated-edge separating lines: h_k(p) = s*w_k(p) + MARGIN*len_k >= 0
        // is necessary for validity.
        float s = (area >= 0.0f) ? 1.0f : -1.0f;
        float4* eg = (float4*)((char*)sf + EDGE_BYTE) + f * 3;
        {
            float cx = s * dy01, cy = -s * dx01;
            float dd = -(cx * a0x + cy * a0y) + MARGIN * sqrtf(l01);
            eg[0] = make_float4(cx, cy, dd, 0.0f);
        }
        {
            float cx = s * dy12, cy = -s * dx12;
            float dd = -(cx * a1x + cy * a1y) + MARGIN * sqrtf(l12);
            eg[1] = make_float4(cx, cy, dd, 0.0f);
        }
        {
            float cx = s * dy20, cy = -s * dx20;
            float dd = -(cx * a2x + cy * a2y) + MARGIN * sqrtf(l20);
            eg[2] = make_float4(cx, cy, dd, 0.0f);
        }
    }
    __syncthreads();

    const int pix = blockIdx.x * PPB + pixLocal;     // may exceed NPIX in last block
    const int pi  = pix >> 7;
    const int pj  = pix & (IMG - 1);
    const float px = 1.0f - (2.0f * ((float)pj + 0.5f)) * (1.0f / (float)IMG);
    const float py = 1.0f - (2.0f * ((float)pi + 0.5f)) * (1.0f / (float)IMG);

    // Span x bounds: 32 consecutive pixels of one row (32-aligned base).
    const int   pj0   = pj & ~31;
    const float pxmax = 1.0f - (2.0f * ((float)pj0 + 0.5f)) * (1.0f / (float)IMG);
    const float pxmin = 1.0f - (2.0f * ((float)(pj0 + 31) + 0.5f)) * (1.0f / (float)IMG);

    const float4* fq  = (const float4*)sf;
    const float4* bbq = (const float4*)(sf + BB_OFF);
    const float4* egq = (const float4*)((char*)sf + EDGE_BYTE);
    uint16_t* slist = (uint16_t*)((char*)sf + LIST_BYTE) + span * NFACE;
    int*      cnts  = (int*)((char*)sf + CNT_BYTE);
    unsigned long long* mrg = (unsigned long long*)((char*)sf + MRG_BYTE);

    // ---- Phase 2a: warp (span, slice) compacts face quarter `slice` for its
    // span into segment `slice` of the shared span list. All 28 warps active.
    {
        const int fbase = slice * FQUART;
        uint16_t* seg = slist + slice * FQUART;
        int count = 0;
#pragma unroll 4
        for (int base = 0; base < FQUART; base += 32) {   // 7 iters (last: 8 lanes)
            int  fl  = base + lane;
            bool inr = fl < FQUART;
            int  f   = fbase + (inr ? fl : 0);
            float4 bb = bbq[f];
            bool hit = inr && (bb.z <= py) && (py <= bb.w) &&
                       (bb.x <= pxmax) && (pxmin <= bb.y);
            if (hit) {
                const float4* eg = egq + f * 3;
                float4 e0 = eg[0], e1 = eg[1], e2 = eg[2];
                float h0 = e0.x * ((e0.x >= 0.0f) ? pxmax : pxmin) + e0.y * py + e0.z;
                float h1 = e1.x * ((e1.x >= 0.0f) ? pxmax : pxmin) + e1.y * py + e1.z;
                float h2 = e2.x * ((e2.x >= 0.0f) ? pxmax : pxmin) + e2.y * py + e2.z;
                hit = (h0 >= 0.0f) && (h1 >= 0.0f) && (h2 >= 0.0f);
            }
            unsigned m = __ballot_sync(0xffffffffu, hit);
            if (hit) {
                int pos = count + __popc(m & ((1u << lane) - 1u));
                seg[pos] = (uint16_t)f;
            }
            count += __popc(m);
        }
        if (lane == 0) cnts[span * NSLICE + slice] = count;
    }
    __syncthreads();

    // ---- Phase 2b: scan. Slice k takes i == k (mod 4) of EVERY segment ->
    // per-slice work balanced to within 4 faces. List reads broadcast per warp.
    const unsigned long long SENT = ~0ull;
    unsigned long long s0 = SENT, s1 = SENT, s2 = SENT, s3 = SENT;

#pragma unroll
    for (int q = 0; q < NSLICE; ++q) {
        const int cq = cnts[span * NSLICE + q];
        const uint16_t* seg = slist + q * FQUART;
#pragma unroll 2
        for (int i = slice; i < cq; i += NSLICE) {
            int f = seg[i];
            const float4* fq5 = fq + f * 5;
            float4 q0 = fq5[0];
            float4 q1 = fq5[1];
            float4 q2 = fq5[2];
            float4 q3 = fq5[3];

            float pa0x = __fsub_rn(px, q0.x), pa0y = __fsub_rn(py, q0.y);
            float pa1x = __fsub_rn(px, q0.z), pa1y = __fsub_rn(py, q0.w);
            float pa2x = __fsub_rn(px, q1.x), pa2y = __fsub_rn(py, q1.y);

            float w0 = __fsub_rn(__fmul_rn(pa1x, q2.y), __fmul_rn(pa1y, q2.x));
            float w1 = __fsub_rn(__fmul_rn(pa2x, q2.w), __fmul_rn(pa2y, q2.z));
            float w2 = __fsub_rn(__fmul_rn(pa0x, q1.w), __fmul_rn(pa0y, q1.z));

            float rd = q3.w;
            float b0 = __fmul_rn(w0, rd);
            float b1 = __fmul_rn(w1, rd);
            float b2 = __fmul_rn(w2, rd);

            float zpix = __fadd_rn(__fadd_rn(__fmul_rn(b0, q3.x), __fmul_rn(b1, q3.y)),
                                   __fmul_rn(b2, q3.z));

            bool inside = (b0 >= 0.0f) && (b1 >= 0.0f) && (b2 >= 0.0f);

            // Degenerates were culled at compaction; scan needs no area flag.
            bool valid;
            if (__all_sync(0xffffffffu, inside)) {
                // whole warp inside: dmin irrelevant for validity
                valid = (zpix > EPSF);
            } else {
                float4 q4 = fq5[4];
                float d01 = seg_dist2(pa0x, pa0y, q1.z, q1.w, q4.x);
                float d12 = seg_dist2(pa1x, pa1y, q2.x, q2.y, q4.y);
                float d20 = seg_dist2(pa2x, pa2y, q2.z, q2.w, q4.z);
                float dmin = fminf(d01, fminf(d12, d20));
                valid = (inside || (dmin < BLURF)) && (zpix > EPSF);
            }

            unsigned long long key =
                valid ? ((((unsigned long long)__float_as_uint(zpix)) << 32) |
                         (unsigned)f)
                      : SENT;
            if (key < s3) {
                bool c0 = key < s0, c1 = key < s1, c2 = key < s2;
                unsigned long long n1 = c1 ? (c0 ? s0 : key) : s1;
                unsigned long long n2 = c2 ? (c1 ? s1 : key) : s2;
                unsigned long long n3 = c2 ? s2 : key;
                s0 = c0 ? key : s0;
                s1 = n1; s2 = n2; s3 = n3;
            }
        }
    }

    // Dump partial top-4 to the merge buffer
    {
        unsigned long long* q = mrg + (pixLocal * 16 + slice * 4);
        q[0] = s0; q[1] = s1; q[2] = s2; q[3] = s3;
    }
    __syncthreads();

    // ---- Phase 3: ALL slices merge; slice k writes rank k (parallel epilogue)
    if (pix < NPIX) {
        const unsigned long long* q = mrg + pixLocal * 16;
        unsigned long long t0 = SENT, t1 = SENT, t2 = SENT, t3 = SENT;
#pragma unroll
        for (int j = 0; j < 16; ++j) {
            unsigned long long key = q[j];
            if (key < t3) {
                bool c0 = key < t0, c1 = key < t1, c2 = key < t2;
                unsigned long long n1 = c1 ? (c0 ? t0 : key) : t1;
                unsigned long long n2 = c2 ? (c1 ? t1 : key) : t2;
                unsigned long long n3 = c2 ? t2 : key;
                t0 = c0 ? key : t0;
                t1 = n1; t2 = n2; t3 = n3;
            }
        }
        unsigned long long mine =
            (slice == 0) ? t0 : (slice == 1) ? t1 : (slice == 2) ? t2 : t3;

        const long long gp = (long long)b * NPIX + pix;
        const long long o  = gp * KTOP + slice;

        float p2f = -1.0f, zb = -1.0f, bb0 = -1.0f, bb1 = -1.0f, bb2 = -1.0f, ds = -1.0f;
        if (mine != SENT) {
            int f = (int)(unsigned)(mine & 0xffffffffu);
            FaceEval e = eval_face(fq + f * 5, px, py);
            p2f = (float)f;
            zb  = __uint_as_float((unsigned)(mine >> 32));
            bb0 = e.b0; bb1 = e.b1; bb2 = e.b2;
            ds  = e.dsign;
        }
        out[o]                    = p2f;
        out[OFF_ZBUF + o]         = zb;
        out[OFF_BARY + 3 * o]     = bb0;
        out[OFF_BARY + 3 * o + 1] = bb1;
        out[OFF_BARY + 3 * o + 2] = bb2;
        out[OFF_DIST + o]         = ds;
    }
}

extern "C" void kernel_launch(void* const* d_in, const int* in_sizes, int n_in,
                              void* d_out, int out_size) {
    const float* verts = (const float*)d_in[0];   // (2, 2000, 3) float32
    const int*   faces = (const int*)d_in[1];     // (800, 3)     int32
    float*       out   = (float*)d_out;

    cudaFuncSetAttribute(raster_kernel,
                         cudaFuncAttributeMaxDynamicSharedMemorySize, SMEM_BYTES);

    dim3 grid(BLKX, NB);   // 148 blocks, 1 per SM; 28 warps/SM
    raster_kernel<<<grid, TPB, SMEM_BYTES>>>(verts, faces, out);
}

// round 12
// speedup vs baseline: 1.1886x; 1.1886x over previous
#include <cuda_runtime.h>
#include <cstdint>

// Problem constants (fixed by the reference: B=2, V=2000, F=800, 128x128, K=4)
#define IMG     128
#define NPIX    (IMG * IMG)
#define NFACE   800
#define NB      2
#define NV      2000
#define KTOP    4
#define EPSF    1e-8f
#define BLURF   0.01f
#define MARGIN  0.101f               // sqrt(BLURF)=0.1 plus fp slack (conservative)
#define FSTRIDE 20                   // floats per face record (5 x float4)

#define PPB     224                  // pixels per block (7 spans of 32)
#define NSLICE  4                    // threads cooperating per pixel
#define TPB     (PPB * NSLICE)       // 896 threads = 28 warps
#define NSPAN   7
#define BLKX    74                   // 74 blocks/batch; 74*7 = 518 spans >= 512
#define NSPAN_IMG 512                // 128 rows * 4 spans/row

// Shared memory layout (bytes):  (identical to the 49.1us kernel)
//   [0,      64000)   face records   (800 * 20 floats)
//   [64000,  76800)   expanded bbox  (800 * float4)
//   [76800, 115200)   edge cull eqs  (800 * 3 float4)
//   [115200,126400)   survivor lists (7 spans * 800 * uint16)
//   [126400,126432)   counts
//   [126432,155104)   merge buffer   (224 pixels * 16 * uint64)
#define BB_OFF      (NFACE * FSTRIDE)
#define EDGE_BYTE   (NFACE * FSTRIDE * 4 + NFACE * 16)   // 76800
#define LIST_BYTE   (EDGE_BYTE + NFACE * 48)             // 115200
#define CNT_BYTE    (LIST_BYTE + NSPAN * NFACE * 2)      // 126400
#define MRG_BYTE    (CNT_BYTE + 32)                      // 126432
#define SMEM_BYTES  (MRG_BYTE + PPB * 16 * 8)            // 155104

// Output layout (float32, concatenated flattened reference outputs)
#define OFF_ZBUF  131072
#define OFF_BARY  262144
#define OFF_DIST  655360

struct FaceEval {
    float b0, b1, b2, zpix, dsign;
    bool  valid;
};

__device__ __forceinline__ float seg_dist2(float pax, float pay,
                                           float abx, float aby, float rl) {
    float num = __fadd_rn(__fmul_rn(pax, abx), __fmul_rn(pay, aby));
    float t   = __fmul_rn(num, rl);
    t = fminf(fmaxf(t, 0.0f), 1.0f);
    float dx = __fsub_rn(pax, __fmul_rn(t, abx));
    float dy = __fsub_rn(pay, __fmul_rn(t, aby));
    return __fadd_rn(__fmul_rn(dx, dx), __fmul_rn(dy, dy));
}

// Field map (5 x float4 per face):
//  q0: a0x a0y a1x a1y
//  q1: a2x a2y dx01 dy01
//  q2: dx12 dy12 dx20 dy20
//  q3: z0 z1 z2 rdenom
//  q4: rl01 rl12 rl20 areaflag
__device__ __forceinline__ FaceEval eval_face(const float4* __restrict__ fq5,
                                              float px, float py) {
    float4 q0 = fq5[0];
    float4 q1 = fq5[1];
    float4 q2 = fq5[2];
    float4 q3 = fq5[3];
    float4 q4 = fq5[4];

    float pa0x = __fsub_rn(px, q0.x), pa0y = __fsub_rn(py, q0.y);
    float pa1x = __fsub_rn(px, q0.z), pa1y = __fsub_rn(py, q0.w);
    float pa2x = __fsub_rn(px, q1.x), pa2y = __fsub_rn(py, q1.y);

    float w0 = __fsub_rn(__fmul_rn(pa1x, q2.y), __fmul_rn(pa1y, q2.x));
    float w1 = __fsub_rn(__fmul_rn(pa2x, q2.w), __fmul_rn(pa2y, q2.z));
    float w2 = __fsub_rn(__fmul_rn(pa0x, q1.w), __fmul_rn(pa0y, q1.z));

    FaceEval e;
    float rd = q3.w;
    e.b0 = __fmul_rn(w0, rd);
    e.b1 = __fmul_rn(w1, rd);
    e.b2 = __fmul_rn(w2, rd);

    e.zpix = __fadd_rn(__fadd_rn(__fmul_rn(e.b0, q3.x), __fmul_rn(e.b1, q3.y)),
                       __fmul_rn(e.b2, q3.z));

    bool inside = (e.b0 >= 0.0f) && (e.b1 >= 0.0f) && (e.b2 >= 0.0f);

    float d01 = seg_dist2(pa0x, pa0y, q1.z, q1.w, q4.x);
    float d12 = seg_dist2(pa1x, pa1y, q2.x, q2.y, q4.y);
    float d20 = seg_dist2(pa2x, pa2y, q2.z, q2.w, q4.z);
    float dmin = fminf(d01, fminf(d12, d20));

    e.dsign = inside ? -dmin : dmin;
    e.valid = (inside || (dmin < BLURF)) && (e.zpix > EPSF) && (q4.w > 0.5f);
    return e;
}

__global__ void __launch_bounds__(TPB, 1)
raster_kernel(const float* __restrict__ verts,
              const int*   __restrict__ faces,
              float*       __restrict__ out) {
    extern __shared__ float sf[];
    const int b    = blockIdx.y;
    const int tid  = threadIdx.x;
    const int lane = tid & 31;

    // Pixel/slice decomposition: warps 0-6 are slice 0 over spans 0-6, etc.
    const int pixLocal = tid % PPB;        // 0..223 (smem indexing within block)
    const int slice    = tid / PPB;        // 0..3
    const int span     = pixLocal >> 5;    // 0..6

    // ---- Phase 1: per-face records + bbox + dilated-edge separation eqs
    const float* vb = verts + (size_t)b * NV * 3;
    for (int f = tid; f < NFACE; f += TPB) {
        int i0 = faces[3 * f + 0];
        int i1 = faces[3 * f + 1];
        int i2 = faces[3 * f + 2];
        float a0x = vb[3 * i0], a0y = vb[3 * i0 + 1], z0 = vb[3 * i0 + 2];
        float a1x = vb[3 * i1], a1y = vb[3 * i1 + 1], z1 = vb[3 * i1 + 2];
        float a2x = vb[3 * i2], a2y = vb[3 * i2 + 1], z2 = vb[3 * i2 + 2];

        float dx01 = __fsub_rn(a1x, a0x), dy01 = __fsub_rn(a1y, a0y);
        float dx12 = __fsub_rn(a2x, a1x), dy12 = __fsub_rn(a2y, a1y);
        float dx20 = __fsub_rn(a0x, a2x), dy20 = __fsub_rn(a0y, a2y);

        float area = __fsub_rn(__fmul_rn(__fsub_rn(a2x, a0x), dy01),
                               __fmul_rn(__fsub_rn(a2y, a0y), dx01));
        bool  big   = fabsf(area) > EPSF;
        float denom = big ? area : ((area >= 0.0f) ? EPSF : -EPSF);

        float l01 = __fadd_rn(__fadd_rn(__fmul_rn(dx01, dx01), __fmul_rn(dy01, dy01)), EPSF);
        float l12 = __fadd_rn(__fadd_rn(__fmul_rn(dx12, dx12), __fmul_rn(dy12, dy12)), EPSF);
        float l20 = __fadd_rn(__fadd_rn(__fmul_rn(dx20, dx20), __fmul_rn(dy20, dy20)), EPSF);

        float* d = sf + f * FSTRIDE;
        d[0]  = a0x;  d[1]  = a0y;  d[2]  = a1x;  d[3]  = a1y;
        d[4]  = a2x;  d[5]  = a2y;  d[6]  = dx01; d[7]  = dy01;
        d[8]  = dx12; d[9]  = dy12; d[10] = dx20; d[11] = dy20;
        d[12] = z0;   d[13] = z1;   d[14] = z2;   d[15] = 1.0f / denom;
        d[16] = 1.0f / l01; d[17] = 1.0f / l12; d[18] = 1.0f / l20;
        d[19] = big ? 1.0f : 0.0f;

        // bbox (expanded). Degenerate faces never valid -> empty bbox culls them.
        float xmn, xmx, ymn, ymx;
        if (big) {
            xmn = fminf(a0x, fminf(a1x, a2x)) - MARGIN;
            xmx = fmaxf(a0x, fmaxf(a1x, a2x)) + MARGIN;
            ymn = fminf(a0y, fminf(a1y, a2y)) - MARGIN;
            ymx = fmaxf(a0y, fmaxf(a1y, a2y)) + MARGIN;
        } else {
            xmn = 1e30f; xmx = -1e30f; ymn = 1e30f; ymx = -1e30f;
        }
        float* bb = sf + BB_OFF + f * 4;
        bb[0] = xmn; bb[1] = xmx; bb[2] = ymn; bb[3] = ymx;

        // Dilated-edge separating lines: h_k(p) = s*w_k(p) + MARGIN*len_k >= 0
        // necessary for validity.
        float s = (area >= 0.0f) ? 1.0f : -1.0f;
        float4* eg = (float4*)((char*)sf + EDGE_BYTE) + f * 3;
        {
            float cx = s * dy01, cy = -s * dx01;
            float dd = -(cx * a0x + cy * a0y) + MARGIN * sqrtf(l01);
            eg[0] = make_float4(cx, cy, dd, 0.0f);
        }
        {
            float cx = s * dy12, cy = -s * dx12;
            float dd = -(cx * a1x + cy * a1y) + MARGIN * sqrtf(l12);
            eg[1] = make_float4(cx, cy, dd, 0.0f);
        }
        {
            float cx = s * dy20, cy = -s * dx20;
            float dd = -(cx * a2x + cy * a2y) + MARGIN * sqrtf(l20);
            eg[2] = make_float4(cx, cy, dd, 0.0f);
        }
    }
    __syncthreads();

    // ---- Row-interleaved span assignment (load balancing across blocks).
    // Global span id with stride-74 interleave: every block gets 7 spans spread
    // uniformly over the image's 128 rows, equalizing per-block survivor load.
    const int g    = span * BLKX + blockIdx.x;       // 0..517
    const bool live = (g < NSPAN_IMG);               // 512 real spans per image
    const int pi  = g >> 2;                          // row 0..127 (when live)
    const int pj0 = (g & 3) * 32;                    // span base column
    const int pj  = pj0 + lane;
    const int pix = pi * IMG + pj;

    const float px = 1.0f - (2.0f * ((float)pj + 0.5f)) * (1.0f / (float)IMG);
    const float py = 1.0f - (2.0f * ((float)pi + 0.5f)) * (1.0f / (float)IMG);
    const float pxmax = 1.0f - (2.0f * ((float)pj0 + 0.5f)) * (1.0f / (float)IMG);
    const float pxmin = 1.0f - (2.0f * ((float)(pj0 + 31) + 0.5f)) * (1.0f / (float)IMG);

    const float4* fq  = (const float4*)sf;
    const float4* bbq = (const float4*)(sf + BB_OFF);
    const float4* egq = (const float4*)((char*)sf + EDGE_BYTE);
    uint16_t* list = (uint16_t*)((char*)sf + LIST_BYTE) + span * NFACE;
    int*      cnts = (int*)((char*)sf + CNT_BYTE);
    unsigned long long* mrg = (unsigned long long*)((char*)sf + MRG_BYTE);

    // ---- Phase 2a: slice-0 warps build per-span survivor lists
    if (slice == 0) {
        int count = 0;
#pragma unroll 5
        for (int base = 0; base < NFACE; base += 32) {
            int f = base + lane;                    // NFACE % 32 == 0
            float4 bb = bbq[f];
            bool hit = live && (bb.z <= py) && (py <= bb.w) &&
                       (bb.x <= pxmax) && (pxmin <= bb.y);
            if (hit) {
                const float4* eg = egq + f * 3;
                float4 e0 = eg[0], e1 = eg[1], e2 = eg[2];
                float h0 = e0.x * ((e0.x >= 0.0f) ? pxmax : pxmin) + e0.y * py + e0.z;
                float h1 = e1.x * ((e1.x >= 0.0f) ? pxmax : pxmin) + e1.y * py + e1.z;
                float h2 = e2.x * ((e2.x >= 0.0f) ? pxmax : pxmin) + e2.y * py + e2.z;
                hit = (h0 >= 0.0f) && (h1 >= 0.0f) && (h2 >= 0.0f);
            }
            unsigned m = __ballot_sync(0xffffffffu, hit);
            if (hit) {
                int pos = count + __popc(m & ((1u << lane) - 1u));
                list[pos] = (uint16_t)f;
            }
            count += __popc(m);
        }
        if (lane == 0) cnts[span] = count;
    }
    __syncthreads();
    const int count = cnts[span];

    // ---- Phase 2b: each slice scans an interleaved quarter of the survivors
    const unsigned long long SENT = ~0ull;
    unsigned long long s0 = SENT, s1 = SENT, s2 = SENT, s3 = SENT;

#pragma unroll 2
    for (int i = slice; i < count; i += NSLICE) {
        int f = list[i];                             // warp-uniform broadcast LDS
        FaceEval e = eval_face(fq + f * 5, px, py);
        unsigned long long key =
            e.valid ? ((((unsigned long long)__float_as_uint(e.zpix)) << 32) |
                       (unsigned)f)
                    : SENT;
        if (key < s3) {
            bool c0 = key < s0, c1 = key < s1, c2 = key < s2;
            unsigned long long n1 = c1 ? (c0 ? s0 : key) : s1;
            unsigned long long n2 = c2 ? (c1 ? s1 : key) : s2;
            unsigned long long n3 = c2 ? s2 : key;
            s0 = c0 ? key : s0;
            s1 = n1; s2 = n2; s3 = n3;
        }
    }

    // Dump partial top-4 to the merge buffer
    {
        unsigned long long* q = mrg + (pixLocal * 16 + slice * 4);
        q[0] = s0; q[1] = s1; q[2] = s2; q[3] = s3;
    }
    __syncthreads();

    // ---- Phase 3: ALL slices merge; slice k writes rank k (parallel epilogue)
    if (live) {
        const unsigned long long* q = mrg + pixLocal * 16;
        unsigned long long t0 = SENT, t1 = SENT, t2 = SENT, t3 = SENT;
#pragma unroll
        for (int j = 0; j < 16; ++j) {
            unsigned long long key = q[j];
            if (key < t3) {
                bool c0 = key < t0, c1 = key < t1, c2 = key < t2;
                unsigned long long n1 = c1 ? (c0 ? t0 : key) : t1;
                unsigned long long n2 = c2 ? (c1 ? t1 : key) : t2;
                unsigned long long n3 = c2 ? t2 : key;
                t0 = c0 ? key : t0;
                t1 = n1; t2 = n2; t3 = n3;
            }
        }
        unsigned long long mine =
            (slice == 0) ? t0 : (slice == 1) ? t1 : (slice == 2) ? t2 : t3;

        const long long gp = (long long)b * NPIX + pix;
        const long long o  = gp * KTOP + slice;

        float p2f = -1.0f, zb = -1.0f, bb0 = -1.0f, bb1 = -1.0f, bb2 = -1.0f, ds = -1.0f;
        if (mine != SENT) {
            int f = (int)(unsigned)(mine & 0xffffffffu);
            FaceEval e = eval_face(fq + f * 5, px, py);
            p2f = (float)f;
            zb  = __uint_as_float((unsigned)(mine >> 32));
            bb0 = e.b0; bb1 = e.b1; bb2 = e.b2;
            ds  = e.dsign;
        }
        out[o]                    = p2f;
        out[OFF_ZBUF + o]         = zb;
        out[OFF_BARY + 3 * o]     = bb0;
        out[OFF_BARY + 3 * o + 1] = bb1;
        out[OFF_BARY + 3 * o + 2] = bb2;
        out[OFF_DIST + o]         = ds;
    }
}

extern "C" void kernel_launch(void* const* d_in, const int* in_sizes, int n_in,
                              void* d_out, int out_size) {
    const float* verts = (const float*)d_in[0];   // (2, 2000, 3) float32
    const int*   faces = (const int*)d_in[1];     // (800, 3)     int32
    float*       out   = (float*)d_out;

    cudaFuncSetAttribute(raster_kernel,
                         cudaFuncAttributeMaxDynamicSharedMemorySize, SMEM_BYTES);

    dim3 grid(BLKX, NB);   // 148 blocks, 1 per SM; 28 warps/SM
    raster_kernel<<<grid, TPB, SMEM_BYTES>>>(verts, faces, out);
}